// round 6
// baseline (speedup 1.0000x reference)
#include <cuda_runtime.h>
#include <math_constants.h>

#define MAX_M   4096
#define DH      128
#define DX      128
#define GEMM_ROWS 16

// Scratch (device globals — no allocation allowed in kernel_launch)
__device__ int   d_seg_start[MAX_M + 1];
__device__ float d_proj[MAX_M * DX];

// ---------------------------------------------------------------------------
// Kernel 1: segment boundaries via binary search (segment_ids is sorted).
// d_seg_start[g] = first index i with seg[i] >= g;  d_seg_start[M] = N.
// ---------------------------------------------------------------------------
__global__ void seg_starts_kernel(const int* __restrict__ seg, int n, int m) {
    int g = blockIdx.x * blockDim.x + threadIdx.x;
    if (g > m) return;
    int lo = 0, hi = n;
    while (lo < hi) {
        int mid = (lo + hi) >> 1;
        if (__ldg(seg + mid) < g) lo = mid + 1; else hi = mid;
    }
    d_seg_start[g] = lo;
}

// ---------------------------------------------------------------------------
// Kernel 2: proj = h @ a   (Mx128 @ 128x128, fp32)
// blocks of 128 threads; each block computes up to 16 rows.
// a tile (64x128) and h tile (16x64) staged in smem; 'a' stays L2-resident.
// ---------------------------------------------------------------------------
__global__ void proj_gemm_kernel(const float* __restrict__ h,
                                 const float* __restrict__ a, int m) {
    __shared__ float a_s[64][DX];         // 32 KB
    __shared__ float h_s[GEMM_ROWS][64];  // 4 KB
    const int tid = threadIdx.x;          // output column
    const int g0  = blockIdx.x * GEMM_ROWS;
    const int nrows = min(GEMM_ROWS, m - g0);

    float acc[GEMM_ROWS];
#pragma unroll
    for (int r = 0; r < GEMM_ROWS; r++) acc[r] = 0.f;

#pragma unroll
    for (int kt = 0; kt < DH / 64; kt++) {
#pragma unroll 8
        for (int t = 0; t < 64; t++)
            a_s[t][tid] = a[(kt * 64 + t) * DX + tid];
        for (int idx = tid; idx < GEMM_ROWS * 64; idx += 128) {
            int r = idx >> 6, kk = idx & 63;
            if (r < nrows)
                h_s[r][kk] = h[(size_t)(g0 + r) * DH + kt * 64 + kk];
        }
        __syncthreads();
#pragma unroll 16
        for (int kk = 0; kk < 64; kk++) {
            float av = a_s[kk][tid];
#pragma unroll
            for (int r = 0; r < GEMM_ROWS; r++)
                acc[r] = fmaf(h_s[r][kk], av, acc[r]);
        }
        __syncthreads();
    }
    for (int r = 0; r < nrows; r++)
        d_proj[(size_t)(g0 + r) * DX + tid] = acc[r];
}

// ---------------------------------------------------------------------------
// Kernel 3: fused score + online segment-softmax + weighted segment sum.
// One CTA per segment (M CTAs, 128 threads = 4 warps).
// Warp w handles 4 nodes per iteration (start+4w+16k .. +3); lane owns dims
// [4*lane, 4*lane+4). Four loads in flight per warp (MLP=4), four shfl-reduce
// chains interleaved. Mainloop is specialized for full quads; a short tail
// loop handles the final <=3 nodes. x is read EXACTLY ONCE from HBM
// (streaming float4), reused from registers for the e*x accumulation.
// ---------------------------------------------------------------------------
__device__ __forceinline__ void online_update(
    float s, const float4& c, float& m, float& z,
    float& ax, float& ay, float& az, float& aw)
{
    if (s > m) {                       // warp-uniform branch (s same on all lanes)
        const float r = __expf(m - s); // first time: exp(-inf)=0, state was 0
        z *= r; ax *= r; ay *= r; az *= r; aw *= r;
        m = s;
    }
    const float e = __expf(s - m);
    z += e;
    ax = fmaf(e, c.x, ax); ay = fmaf(e, c.y, ay);
    az = fmaf(e, c.z, az); aw = fmaf(e, c.w, aw);
}

__global__ void __launch_bounds__(128)
attn_kernel(const float* __restrict__ x, float* __restrict__ out) {
    const int g    = blockIdx.x;
    const int tid  = threadIdx.x;
    const int w    = tid >> 5;
    const int lane = tid & 31;

    const int start = d_seg_start[g];
    const int end   = d_seg_start[g + 1];

    const float4 p = reinterpret_cast<const float4*>(d_proj + (size_t)g * DX)[lane];
    const float4* __restrict__ xv4 = reinterpret_cast<const float4*>(x);

    float m = -CUDART_INF_F;
    float z = 0.f;
    float ax = 0.f, ay = 0.f, az = 0.f, aw = 0.f;

    int i = start + 4 * w;            // this warp's first node quad
    float4 v0 = {0,0,0,0}, v1 = {0,0,0,0}, v2 = {0,0,0,0}, v3 = {0,0,0,0};
    if (i     < end) v0 = __ldcs(xv4 + (size_t)(i    ) * (DX / 4) + lane);
    if (i + 1 < end) v1 = __ldcs(xv4 + (size_t)(i + 1) * (DX / 4) + lane);
    if (i + 2 < end) v2 = __ldcs(xv4 + (size_t)(i + 2) * (DX / 4) + lane);
    if (i + 3 < end) v3 = __ldcs(xv4 + (size_t)(i + 3) * (DX / 4) + lane);

    // ---- fast path: full quads, no per-node predication ----
    while (i + 4 <= end) {
        const float4 c0 = v0, c1 = v1, c2 = v2, c3 = v3;
        const int inext = i + 16;
        if (inext     < end) v0 = __ldcs(xv4 + (size_t)(inext    ) * (DX / 4) + lane);
        if (inext + 1 < end) v1 = __ldcs(xv4 + (size_t)(inext + 1) * (DX / 4) + lane);
        if (inext + 2 < end) v2 = __ldcs(xv4 + (size_t)(inext + 2) * (DX / 4) + lane);
        if (inext + 3 < end) v3 = __ldcs(xv4 + (size_t)(inext + 3) * (DX / 4) + lane);

        float s0 = c0.x * p.x + c0.y * p.y + c0.z * p.z + c0.w * p.w;
        float s1 = c1.x * p.x + c1.y * p.y + c1.z * p.z + c1.w * p.w;
        float s2 = c2.x * p.x + c2.y * p.y + c2.z * p.z + c2.w * p.w;
        float s3 = c3.x * p.x + c3.y * p.y + c3.z * p.z + c3.w * p.w;
#pragma unroll
        for (int off = 16; off > 0; off >>= 1) {       // interleaved chains
            s0 += __shfl_xor_sync(0xffffffffu, s0, off);
            s1 += __shfl_xor_sync(0xffffffffu, s1, off);
            s2 += __shfl_xor_sync(0xffffffffu, s2, off);
            s3 += __shfl_xor_sync(0xffffffffu, s3, off);
        }

        online_update(s0, c0, m, z, ax, ay, az, aw);
        online_update(s1, c1, m, z, ax, ay, az, aw);
        online_update(s2, c2, m, z, ax, ay, az, aw);
        online_update(s3, c3, m, z, ax, ay, az, aw);

        i = inext;
    }

    // ---- tail: 1..3 remaining nodes for this warp ----
    if (i < end) {
        const int rem = end - i;       // 1..3
        float s0 = v0.x * p.x + v0.y * p.y + v0.z * p.z + v0.w * p.w;
        float s1 = v1.x * p.x + v1.y * p.y + v1.z * p.z + v1.w * p.w;
        float s2 = v2.x * p.x + v2.y * p.y + v2.z * p.z + v2.w * p.w;
#pragma unroll
        for (int off = 16; off > 0; off >>= 1) {
            s0 += __shfl_xor_sync(0xffffffffu, s0, off);
            s1 += __shfl_xor_sync(0xffffffffu, s1, off);
            s2 += __shfl_xor_sync(0xffffffffu, s2, off);
        }
        online_update(s0, v0, m, z, ax, ay, az, aw);
        if (rem > 1) online_update(s1, v1, m, z, ax, ay, az, aw);
        if (rem > 2) online_update(s2, v2, m, z, ax, ay, az, aw);
    }

    // Combine 4 warps' (m, z, acc) in smem.
    __shared__ float m_s[4], z_s[4];
    __shared__ float acc_s[4][DX];
    acc_s[w][lane * 4 + 0] = ax;
    acc_s[w][lane * 4 + 1] = ay;
    acc_s[w][lane * 4 + 2] = az;
    acc_s[w][lane * 4 + 3] = aw;
    if (lane == 0) { m_s[w] = m; z_s[w] = z; }
    __syncthreads();

    const float Mx = fmaxf(fmaxf(m_s[0], m_s[1]), fmaxf(m_s[2], m_s[3]));
    float Z = 0.f, A = 0.f;
    if (Mx > -CUDART_INF_F) {   // false only for an empty segment
#pragma unroll
        for (int ww = 0; ww < 4; ww++) {
            const float c = __expf(m_s[ww] - Mx);  // -inf warp -> 0
            Z = fmaf(z_s[ww], c, Z);
            A = fmaf(acc_s[ww][tid], c, A);
        }
    }
    out[(size_t)g * DX + tid] = (Z > 0.f) ? (A / Z) : 0.f;
}

// ---------------------------------------------------------------------------
extern "C" void kernel_launch(void* const* d_in, const int* in_sizes, int n_in,
                              void* d_out, int out_size) {
    const float* h   = (const float*)d_in[0];
    const float* x   = (const float*)d_in[1];
    const float* a   = (const float*)d_in[2];
    const int*   seg = (const int*)d_in[3];
    float* out = (float*)d_out;

    int m = in_sizes[0] / DH;         // number of graphs
    int n = in_sizes[3];              // number of nodes
    if (m > MAX_M) m = MAX_M;         // scratch capacity guard

    seg_starts_kernel<<<(m + 1 + 255) / 256, 256>>>(seg, n, m);
    proj_gemm_kernel<<<(m + GEMM_ROWS - 1) / GEMM_ROWS, 128>>>(h, a, m);
    attn_kernel<<<m, 128>>>(x, out);
}

// round 13
// speedup vs baseline: 1.0119x; 1.0119x over previous
#include <cuda_runtime.h>
#include <math_constants.h>

#define MAX_M   4096
#define DH      128
#define DX      128
#define GEMM_ROWS 16
#define PREP_THREADS 128

// Scratch (device globals — no allocation allowed in kernel_launch)
__device__ int   d_seg_start[MAX_M + 1];
__device__ float d_proj[MAX_M * DX];

// ---------------------------------------------------------------------------
// Kernel 1 (fused prep): blocks [0, gemm_blocks) compute proj = h @ a;
// blocks [gemm_blocks, ...) compute segment boundaries by scatter.
//
// Boundary scatter: segment_ids sorted => for g in (seg[i-1], seg[i]],
// d_seg_start[g] = i (first index with seg >= g). Thread i handles that
// range; thread n-1 also fills (seg[n-1], m] with n. Coalesced single pass,
// no dependent-load chains (replaces an 11.5us binary-search kernel).
// ---------------------------------------------------------------------------
__global__ void __launch_bounds__(PREP_THREADS)
prep_kernel(const float* __restrict__ h, const float* __restrict__ a,
            const int* __restrict__ seg, int n, int m, int gemm_blocks) {
    const int tid = threadIdx.x;

    if ((int)blockIdx.x >= gemm_blocks) {
        // ---- segment-boundary scatter ----
        const int i = (blockIdx.x - gemm_blocks) * PREP_THREADS + tid;
        if (i < n) {
            const int b  = __ldg(seg + i);
            const int a0 = (i == 0) ? -1 : __ldg(seg + i - 1);
            for (int g = a0 + 1; g <= b; g++)   // empty range if seg[i-1]==seg[i]
                d_seg_start[g] = i;
            if (i == n - 1) {
                for (int g = b + 1; g <= m; g++)
                    d_seg_start[g] = n;         // trailing empty segments + sentinel
            }
        }
        return;
    }

    // ---- proj = h @ a  (GEMM_ROWS rows per block) ----
    __shared__ float a_s[64][DX];         // 32 KB
    __shared__ float h_s[GEMM_ROWS][64];  // 4 KB
    const int g0    = blockIdx.x * GEMM_ROWS;
    const int nrows = min(GEMM_ROWS, m - g0);

    float acc[GEMM_ROWS];
#pragma unroll
    for (int r = 0; r < GEMM_ROWS; r++) acc[r] = 0.f;

#pragma unroll
    for (int kt = 0; kt < DH / 64; kt++) {
#pragma unroll 8
        for (int t = 0; t < 64; t++)
            a_s[t][tid] = a[(kt * 64 + t) * DX + tid];
        for (int idx = tid; idx < GEMM_ROWS * 64; idx += PREP_THREADS) {
            int r = idx >> 6, kk = idx & 63;
            if (r < nrows)
                h_s[r][kk] = h[(size_t)(g0 + r) * DH + kt * 64 + kk];
        }
        __syncthreads();
#pragma unroll 16
        for (int kk = 0; kk < 64; kk++) {
            float av = a_s[kk][tid];
#pragma unroll
            for (int r = 0; r < GEMM_ROWS; r++)
                acc[r] = fmaf(h_s[r][kk], av, acc[r]);
        }
        __syncthreads();
    }
    for (int r = 0; r < nrows; r++)
        d_proj[(size_t)(g0 + r) * DX + tid] = acc[r];
}

// ---------------------------------------------------------------------------
// Kernel 2: fused score + online segment-softmax + weighted segment sum.
// One CTA per segment (M CTAs, 128 threads = 4 warps).
// Warp w handles 4 nodes per iteration (start+4w+16k .. +3); lane owns dims
// [4*lane, 4*lane+4). Four loads in flight per warp (MLP=4), four shfl-reduce
// chains interleaved. Mainloop specialized for full quads; short tail for the
// final <=3 nodes. x is read EXACTLY ONCE from HBM (streaming float4),
// reused from registers for the e*x accumulation.
// ---------------------------------------------------------------------------
__device__ __forceinline__ void online_update(
    float s, const float4& c, float& m, float& z,
    float& ax, float& ay, float& az, float& aw)
{
    if (s > m) {                       // warp-uniform branch (s same on all lanes)
        const float r = __expf(m - s); // first time: exp(-inf)=0, state was 0
        z *= r; ax *= r; ay *= r; az *= r; aw *= r;
        m = s;
    }
    const float e = __expf(s - m);
    z += e;
    ax = fmaf(e, c.x, ax); ay = fmaf(e, c.y, ay);
    az = fmaf(e, c.z, az); aw = fmaf(e, c.w, aw);
}

__global__ void __launch_bounds__(128)
attn_kernel(const float* __restrict__ x, float* __restrict__ out) {
    const int g    = blockIdx.x;
    const int tid  = threadIdx.x;
    const int w    = tid >> 5;
    const int lane = tid & 31;

    const int start = d_seg_start[g];
    const int end   = d_seg_start[g + 1];

    const float4 p = reinterpret_cast<const float4*>(d_proj + (size_t)g * DX)[lane];
    const float4* __restrict__ xv4 = reinterpret_cast<const float4*>(x);

    float m = -CUDART_INF_F;
    float z = 0.f;
    float ax = 0.f, ay = 0.f, az = 0.f, aw = 0.f;

    int i = start + 4 * w;            // this warp's first node quad
    float4 v0 = {0,0,0,0}, v1 = {0,0,0,0}, v2 = {0,0,0,0}, v3 = {0,0,0,0};
    if (i     < end) v0 = __ldcs(xv4 + (size_t)(i    ) * (DX / 4) + lane);
    if (i + 1 < end) v1 = __ldcs(xv4 + (size_t)(i + 1) * (DX / 4) + lane);
    if (i + 2 < end) v2 = __ldcs(xv4 + (size_t)(i + 2) * (DX / 4) + lane);
    if (i + 3 < end) v3 = __ldcs(xv4 + (size_t)(i + 3) * (DX / 4) + lane);

    // ---- fast path: full quads, no per-node predication ----
    while (i + 4 <= end) {
        const float4 c0 = v0, c1 = v1, c2 = v2, c3 = v3;
        const int inext = i + 16;
        if (inext     < end) v0 = __ldcs(xv4 + (size_t)(inext    ) * (DX / 4) + lane);
        if (inext + 1 < end) v1 = __ldcs(xv4 + (size_t)(inext + 1) * (DX / 4) + lane);
        if (inext + 2 < end) v2 = __ldcs(xv4 + (size_t)(inext + 2) * (DX / 4) + lane);
        if (inext + 3 < end) v3 = __ldcs(xv4 + (size_t)(inext + 3) * (DX / 4) + lane);

        float s0 = c0.x * p.x + c0.y * p.y + c0.z * p.z + c0.w * p.w;
        float s1 = c1.x * p.x + c1.y * p.y + c1.z * p.z + c1.w * p.w;
        float s2 = c2.x * p.x + c2.y * p.y + c2.z * p.z + c2.w * p.w;
        float s3 = c3.x * p.x + c3.y * p.y + c3.z * p.z + c3.w * p.w;
#pragma unroll
        for (int off = 16; off > 0; off >>= 1) {       // interleaved chains
            s0 += __shfl_xor_sync(0xffffffffu, s0, off);
            s1 += __shfl_xor_sync(0xffffffffu, s1, off);
            s2 += __shfl_xor_sync(0xffffffffu, s2, off);
            s3 += __shfl_xor_sync(0xffffffffu, s3, off);
        }

        online_update(s0, c0, m, z, ax, ay, az, aw);
        online_update(s1, c1, m, z, ax, ay, az, aw);
        online_update(s2, c2, m, z, ax, ay, az, aw);
        online_update(s3, c3, m, z, ax, ay, az, aw);

        i = inext;
    }

    // ---- tail: 1..3 remaining nodes for this warp ----
    if (i < end) {
        const int rem = end - i;       // 1..3
        float s0 = v0.x * p.x + v0.y * p.y + v0.z * p.z + v0.w * p.w;
        float s1 = v1.x * p.x + v1.y * p.y + v1.z * p.z + v1.w * p.w;
        float s2 = v2.x * p.x + v2.y * p.y + v2.z * p.z + v2.w * p.w;
#pragma unroll
        for (int off = 16; off > 0; off >>= 1) {
            s0 += __shfl_xor_sync(0xffffffffu, s0, off);
            s1 += __shfl_xor_sync(0xffffffffu, s1, off);
            s2 += __shfl_xor_sync(0xffffffffu, s2, off);
        }
        online_update(s0, v0, m, z, ax, ay, az, aw);
        if (rem > 1) online_update(s1, v1, m, z, ax, ay, az, aw);
        if (rem > 2) online_update(s2, v2, m, z, ax, ay, az, aw);
    }

    // Combine 4 warps' (m, z, acc) in smem.
    __shared__ float m_s[4], z_s[4];
    __shared__ float acc_s[4][DX];
    acc_s[w][lane * 4 + 0] = ax;
    acc_s[w][lane * 4 + 1] = ay;
    acc_s[w][lane * 4 + 2] = az;
    acc_s[w][lane * 4 + 3] = aw;
    if (lane == 0) { m_s[w] = m; z_s[w] = z; }
    __syncthreads();

    const float Mx = fmaxf(fmaxf(m_s[0], m_s[1]), fmaxf(m_s[2], m_s[3]));
    float Z = 0.f, A = 0.f;
    if (Mx > -CUDART_INF_F) {   // false only for an empty segment
#pragma unroll
        for (int ww = 0; ww < 4; ww++) {
            const float c = __expf(m_s[ww] - Mx);  // -inf warp -> 0
            Z = fmaf(z_s[ww], c, Z);
            A = fmaf(acc_s[ww][tid], c, A);
        }
    }
    __stcs(out + (size_t)g * DX + tid, (Z > 0.f) ? (A / Z) : 0.f);  // streaming store
}

// ---------------------------------------------------------------------------
extern "C" void kernel_launch(void* const* d_in, const int* in_sizes, int n_in,
                              void* d_out, int out_size) {
    const float* h   = (const float*)d_in[0];
    const float* x   = (const float*)d_in[1];
    const float* a   = (const float*)d_in[2];
    const int*   seg = (const int*)d_in[3];
    float* out = (float*)d_out;

    int m = in_sizes[0] / DH;         // number of graphs
    int n = in_sizes[3];              // number of nodes
    if (m > MAX_M) m = MAX_M;         // scratch capacity guard

    const int gemm_blocks    = (m + GEMM_ROWS - 1) / GEMM_ROWS;
    const int scatter_blocks = (n + PREP_THREADS - 1) / PREP_THREADS;

    prep_kernel<<<gemm_blocks + scatter_blocks, PREP_THREADS>>>(h, a, seg, n, m, gemm_blocks);
    attn_kernel<<<m, 128>>>(x, out);
}